// round 3
// baseline (speedup 1.0000x reference)
#include <cuda_runtime.h>
#include <cuda_bf16.h>
#include <mma.h>

using namespace nvcuda;

#define HIDDEN 2048
#define INTER  5632
#define NCODES 4096
#define VEC    8
#define MAX_TOKENS 4096

// ---------------- scratch (static device globals: no allocations) ----------------
__device__ float g_wgate[(size_t)INTER * HIDDEN];     // 46 MB
__device__ float g_wup  [(size_t)INTER * HIDDEN];     // 46 MB
__device__ float g_wdown[(size_t)HIDDEN * INTER];     // 46 MB
__device__ float g_h    [(size_t)MAX_TOKENS * INTER]; // 92 MB

// ---------------- dequant: w[r, c*8..c*8+7] = codebook[idx[r,c]] * scale[r] -------
__device__ __forceinline__ void dequant_impl(const float* __restrict__ cb,
                                             const int*   __restrict__ idx,
                                             const float* __restrict__ scale,
                                             float*       __restrict__ w,
                                             int rows, int colsv) {
    int t = blockIdx.x * blockDim.x + threadIdx.x;
    if (t >= rows * colsv) return;
    int r = t / colsv;
    int code = idx[t];
    float s = __ldg(scale + r);
    const float4* cv = reinterpret_cast<const float4*>(cb) + (size_t)code * 2;
    float4 lo = cv[0], hi = cv[1];
    float4* out = reinterpret_cast<float4*>(w) + (size_t)t * 2;
    out[0] = make_float4(lo.x * s, lo.y * s, lo.z * s, lo.w * s);
    out[1] = make_float4(hi.x * s, hi.y * s, hi.z * s, hi.w * s);
}

__global__ void dequant_gate(const float* cb, const int* idx, const float* sc) {
    dequant_impl(cb, idx, sc, g_wgate, INTER, HIDDEN / VEC);
}
__global__ void dequant_up(const float* cb, const int* idx, const float* sc) {
    dequant_impl(cb, idx, sc, g_wup, INTER, HIDDEN / VEC);
}
__global__ void dequant_down(const float* cb, const int* idx, const float* sc) {
    dequant_impl(cb, idx, sc, g_wdown, HIDDEN, INTER / VEC);
}

// ---------------- TF32 WMMA GEMM tiles ----------------
// Block tile 128x64, BK=16, 256 threads = 8 warps in a 4(m) x 2(n) grid.
// Each warp computes a 32x32 slab via a 2x2 grid of 16x16 accumulators.
#define BM 128
#define BN 64
#define BK 16
#define LDS 24   // padded smem leading dim (24 floats)

// GEMM1: gate = x @ Wg^T, up = x @ Wu^T, h = silu(gate) * up
// A = x [M, HIDDEN] row-major; Wg/Wu [INTER, HIDDEN] row-major == col-major B.
__global__ __launch_bounds__(256) void gemm_gateup(const float* __restrict__ A, int M) {
    __shared__ __align__(32) float sA [BM][LDS];
    __shared__ __align__(32) float sBg[BN][LDS];
    __shared__ __align__(32) float sBu[BN][LDS];

    const int K = HIDDEN, N = INTER;
    const int bm = blockIdx.y * BM;
    const int bn = blockIdx.x * BN;
    const int tid = threadIdx.x;
    const int wid = tid >> 5;
    const int wm = wid >> 1;        // 0..3  -> 32-row slab
    const int wn = wid & 1;         // 0..1  -> 32-col slab

    wmma::fragment<wmma::accumulator, 16, 16, 8, float> accg[2][2], accu[2][2];
#pragma unroll
    for (int i = 0; i < 2; i++)
#pragma unroll
        for (int j = 0; j < 2; j++) {
            wmma::fill_fragment(accg[i][j], 0.0f);
            wmma::fill_fragment(accu[i][j], 0.0f);
        }

    const int row = tid >> 2;          // 0..63
    const int c4  = (tid & 3) << 2;    // 0,4,8,12

    for (int k0 = 0; k0 < K; k0 += BK) {
        // global loads issued before the barrier so they overlap prior MMAs
        float4 va0 = *reinterpret_cast<const float4*>(A + (size_t)(bm + row) * K + k0 + c4);
        float4 va1 = *reinterpret_cast<const float4*>(A + (size_t)(bm + 64 + row) * K + k0 + c4);
        float4 vg  = *reinterpret_cast<const float4*>(g_wgate + (size_t)(bn + row) * K + k0 + c4);
        float4 vu  = *reinterpret_cast<const float4*>(g_wup   + (size_t)(bn + row) * K + k0 + c4);
        __syncthreads();
        *reinterpret_cast<float4*>(&sA [row]      [c4]) = va0;
        *reinterpret_cast<float4*>(&sA [row + 64] [c4]) = va1;
        *reinterpret_cast<float4*>(&sBg[row][c4]) = vg;
        *reinterpret_cast<float4*>(&sBu[row][c4]) = vu;
        __syncthreads();

#pragma unroll
        for (int kk = 0; kk < BK; kk += 8) {
            wmma::fragment<wmma::matrix_a, 16, 16, 8, wmma::precision::tf32, wmma::row_major> fa[2];
#pragma unroll
            for (int i = 0; i < 2; i++) {
                wmma::load_matrix_sync(fa[i], &sA[wm * 32 + i * 16][kk], LDS);
#pragma unroll
                for (int e = 0; e < fa[i].num_elements; e++) fa[i].x[e] = wmma::__float_to_tf32(fa[i].x[e]);
            }
#pragma unroll
            for (int j = 0; j < 2; j++) {
                wmma::fragment<wmma::matrix_b, 16, 16, 8, wmma::precision::tf32, wmma::col_major> fbg, fbu;
                wmma::load_matrix_sync(fbg, &sBg[wn * 32 + j * 16][kk], LDS);
                wmma::load_matrix_sync(fbu, &sBu[wn * 32 + j * 16][kk], LDS);
#pragma unroll
                for (int e = 0; e < fbg.num_elements; e++) {
                    fbg.x[e] = wmma::__float_to_tf32(fbg.x[e]);
                    fbu.x[e] = wmma::__float_to_tf32(fbu.x[e]);
                }
#pragma unroll
                for (int i = 0; i < 2; i++) {
                    wmma::mma_sync(accg[i][j], fa[i], fbg, accg[i][j]);
                    wmma::mma_sync(accu[i][j], fa[i], fbu, accu[i][j]);
                }
            }
        }
    }

    // epilogue: h = silu(g) * u (identical accumulator layouts elementwise)
#pragma unroll
    for (int i = 0; i < 2; i++)
#pragma unroll
        for (int j = 0; j < 2; j++) {
#pragma unroll
            for (int e = 0; e < accg[i][j].num_elements; e++) {
                float g = accg[i][j].x[e];
                float u = accu[i][j].x[e];
                float sg = 1.0f / (1.0f + expf(-g));
                accg[i][j].x[e] = g * sg * u;
            }
            wmma::store_matrix_sync(g_h + (size_t)(bm + wm * 32 + i * 16) * N + bn + wn * 32 + j * 16,
                                    accg[i][j], N, wmma::mem_row_major);
        }
}

// GEMM2: out = h @ Wd^T.  A = h [M, INTER]; Wd [HIDDEN, INTER] row-major == col-major B.
__global__ __launch_bounds__(256) void gemm_down(float* __restrict__ out, int M) {
    __shared__ __align__(32) float sA[BM][LDS];
    __shared__ __align__(32) float sB[BN][LDS];

    const int K = INTER, N = HIDDEN;
    const int bm = blockIdx.y * BM;
    const int bn = blockIdx.x * BN;
    const int tid = threadIdx.x;
    const int wid = tid >> 5;
    const int wm = wid >> 1;
    const int wn = wid & 1;

    wmma::fragment<wmma::accumulator, 16, 16, 8, float> acc[2][2];
#pragma unroll
    for (int i = 0; i < 2; i++)
#pragma unroll
        for (int j = 0; j < 2; j++) wmma::fill_fragment(acc[i][j], 0.0f);

    const int row = tid >> 2;
    const int c4  = (tid & 3) << 2;

    for (int k0 = 0; k0 < K; k0 += BK) {
        float4 va0 = *reinterpret_cast<const float4*>(g_h + (size_t)(bm + row) * K + k0 + c4);
        float4 va1 = *reinterpret_cast<const float4*>(g_h + (size_t)(bm + 64 + row) * K + k0 + c4);
        float4 vb  = *reinterpret_cast<const float4*>(g_wdown + (size_t)(bn + row) * K + k0 + c4);
        __syncthreads();
        *reinterpret_cast<float4*>(&sA[row]     [c4]) = va0;
        *reinterpret_cast<float4*>(&sA[row + 64][c4]) = va1;
        *reinterpret_cast<float4*>(&sB[row][c4]) = vb;
        __syncthreads();

#pragma unroll
        for (int kk = 0; kk < BK; kk += 8) {
            wmma::fragment<wmma::matrix_a, 16, 16, 8, wmma::precision::tf32, wmma::row_major> fa[2];
#pragma unroll
            for (int i = 0; i < 2; i++) {
                wmma::load_matrix_sync(fa[i], &sA[wm * 32 + i * 16][kk], LDS);
#pragma unroll
                for (int e = 0; e < fa[i].num_elements; e++) fa[i].x[e] = wmma::__float_to_tf32(fa[i].x[e]);
            }
#pragma unroll
            for (int j = 0; j < 2; j++) {
                wmma::fragment<wmma::matrix_b, 16, 16, 8, wmma::precision::tf32, wmma::col_major> fb;
                wmma::load_matrix_sync(fb, &sB[wn * 32 + j * 16][kk], LDS);
#pragma unroll
                for (int e = 0; e < fb.num_elements; e++) fb.x[e] = wmma::__float_to_tf32(fb.x[e]);
#pragma unroll
                for (int i = 0; i < 2; i++)
                    wmma::mma_sync(acc[i][j], fa[i], fb, acc[i][j]);
            }
        }
    }

#pragma unroll
    for (int i = 0; i < 2; i++)
#pragma unroll
        for (int j = 0; j < 2; j++)
            wmma::store_matrix_sync(out + (size_t)(bm + wm * 32 + i * 16) * N + bn + wn * 32 + j * 16,
                                    acc[i][j], N, wmma::mem_row_major);
}

// ---------------- launch ----------------
extern "C" void kernel_launch(void* const* d_in, const int* in_sizes, int n_in,
                              void* d_out, int out_size) {
    const float* x    = (const float*)d_in[0];
    const float* cbg  = (const float*)d_in[1];
    const int*   idxg = (const int*)  d_in[2];
    const float* scg  = (const float*)d_in[3];
    const float* cbu  = (const float*)d_in[4];
    const int*   idxu = (const int*)  d_in[5];
    const float* scu  = (const float*)d_in[6];
    const float* cbd  = (const float*)d_in[7];
    const int*   idxd = (const int*)  d_in[8];
    const float* scd  = (const float*)d_in[9];
    float* out = (float*)d_out;

    const int M = in_sizes[0] / HIDDEN;   // 4096

    // dequant all three weight matrices
    {
        int n_gu = INTER * (HIDDEN / VEC);
        int n_d  = HIDDEN * (INTER / VEC);
        dequant_gate<<<(n_gu + 255) / 256, 256>>>(cbg, idxg, scg);
        dequant_up  <<<(n_gu + 255) / 256, 256>>>(cbu, idxu, scu);
        dequant_down<<<(n_d  + 255) / 256, 256>>>(cbd, idxd, scd);
    }

    // fused gate/up projection + SwiGLU
    {
        dim3 grid(INTER / BN, M / BM);
        gemm_gateup<<<grid, 256>>>(x, M);
    }

    // down projection
    {
        dim3 grid(HIDDEN / BN, M / BM);
        gemm_down<<<grid, 256>>>(out, M);
    }
}

// round 12
// speedup vs baseline: 1.9986x; 1.9986x over previous
#include <cuda_runtime.h>
#include <cstdint>

#define HIDDEN 2048
#define INTER  5632
#define VEC    8
#define MAXTOK 4096

// ---------------- scratch (device globals: no allocations) ----------------
__device__ float g_wgate[(size_t)INTER * HIDDEN];
__device__ float g_wup  [(size_t)INTER * HIDDEN];
__device__ float g_wdown[(size_t)HIDDEN * INTER];
__device__ float g_x    [(size_t)MAXTOK * HIDDEN];
__device__ float g_gate [(size_t)MAXTOK * INTER];
__device__ float g_up   [(size_t)MAXTOK * INTER];
__device__ float g_h    [(size_t)MAXTOK * INTER];

// ---------------- helpers ----------------
__device__ __forceinline__ float tf32_rn(float x) {
    uint32_t u = __float_as_uint(x);
    u += 0xFFFu + ((u >> 13) & 1u);   // RN-even into tf32 (data has no inf/nan)
    u &= 0xFFFFE000u;
    return __uint_as_float(u);
}

__device__ __forceinline__ uint32_t smem_u32(const void* p) {
    uint32_t a;
    asm("{ .reg .u64 t; cvta.to.shared.u64 t, %1; cvt.u32.u64 %0, t; }" : "=r"(a) : "l"(p));
    return a;
}

__device__ __forceinline__ void cp_async16(uint32_t s, const void* g) {
    asm volatile("cp.async.cg.shared.global [%0], [%1], 16;" :: "r"(s), "l"(g));
}
#define CP_COMMIT() asm volatile("cp.async.commit_group;" ::: "memory")
#define CP_WAIT2()  asm volatile("cp.async.wait_group 2;" ::: "memory")

__device__ __forceinline__ void mma_tf32(float* c, const uint32_t* a, const uint32_t* b) {
    asm volatile(
        "mma.sync.aligned.m16n8k8.row.col.f32.tf32.tf32.f32 "
        "{%0,%1,%2,%3}, {%4,%5,%6,%7}, {%8,%9}, {%0,%1,%2,%3};"
        : "+f"(c[0]), "+f"(c[1]), "+f"(c[2]), "+f"(c[3])
        : "r"(a[0]), "r"(a[1]), "r"(a[2]), "r"(a[3]), "r"(b[0]), "r"(b[1]));
}

// ---------------- prep kernels (tf32-round everything once) ----------------
__device__ __forceinline__ void dequant_impl(const float* __restrict__ cb,
                                             const int*   __restrict__ idx,
                                             const float* __restrict__ scale,
                                             float*       __restrict__ w,
                                             int rows, int colsv) {
    int t = blockIdx.x * blockDim.x + threadIdx.x;
    if (t >= rows * colsv) return;
    int r = t / colsv;
    int code = idx[t];
    float s = __ldg(scale + r);
    const float4* cv = reinterpret_cast<const float4*>(cb) + (size_t)code * 2;
    float4 lo = cv[0], hi = cv[1];
    float4* out = reinterpret_cast<float4*>(w) + (size_t)t * 2;
    out[0] = make_float4(tf32_rn(lo.x * s), tf32_rn(lo.y * s), tf32_rn(lo.z * s), tf32_rn(lo.w * s));
    out[1] = make_float4(tf32_rn(hi.x * s), tf32_rn(hi.y * s), tf32_rn(hi.z * s), tf32_rn(hi.w * s));
}
__global__ void dequant_gate(const float* cb, const int* idx, const float* sc) {
    dequant_impl(cb, idx, sc, g_wgate, INTER, HIDDEN / VEC);
}
__global__ void dequant_up(const float* cb, const int* idx, const float* sc) {
    dequant_impl(cb, idx, sc, g_wup, INTER, HIDDEN / VEC);
}
__global__ void dequant_down(const float* cb, const int* idx, const float* sc) {
    dequant_impl(cb, idx, sc, g_wdown, HIDDEN, INTER / VEC);
}
__global__ void convert_x(const float* __restrict__ x, int n4) {
    int t = blockIdx.x * blockDim.x + threadIdx.x;
    if (t >= n4) return;
    float4 v = reinterpret_cast<const float4*>(x)[t];
    reinterpret_cast<float4*>(g_x)[t] =
        make_float4(tf32_rn(v.x), tf32_rn(v.y), tf32_rn(v.z), tf32_rn(v.w));
}
// h = tf32(silu(gate) * up)
__global__ void silu_mul(int n4) {
    int t = blockIdx.x * blockDim.x + threadIdx.x;
    if (t >= n4) return;
    float4 g = reinterpret_cast<const float4*>(g_gate)[t];
    float4 u = reinterpret_cast<const float4*>(g_up)[t];
    float4 h;
    h.x = tf32_rn(g.x / (1.0f + expf(-g.x)) * u.x);
    h.y = tf32_rn(g.y / (1.0f + expf(-g.y)) * u.y);
    h.z = tf32_rn(g.z / (1.0f + expf(-g.z)) * u.z);
    h.w = tf32_rn(g.w / (1.0f + expf(-g.w)) * u.w);
    reinterpret_cast<float4*>(g_h)[t] = h;
}

// ---------------- TF32 mma.sync GEMM: C[M,N] = A[M,K] @ W[N,K]^T ----------------
// CTA 128x128, BK=32, 3-stage cp.async pipeline, 256 threads = 8 warps (2m x 4n),
// warp tile 64x32 via m16n8k8 frags (4 mi x 4 ni). Smem rows padded to 36 floats
// (LDS pattern 4*g+q hits all 32 banks -> conflict-free).
#define BM 128
#define BN 128
#define BK 32
#define LDSW 36
#define STAGE_FLOATS (2 * BM * LDSW)   // A tile + B tile
#define GEMM_SMEM (3 * STAGE_FLOATS * 4)

__global__ __launch_bounds__(256, 1) void gemm_tf32(const float* __restrict__ A,
                                                    const float* __restrict__ W,
                                                    float* __restrict__ C,
                                                    int M, int N, int K) {
    extern __shared__ float smem[];
    const int tid = threadIdx.x;
    const int warp = tid >> 5, lane = tid & 31;
    const int wm = warp & 1, wn = warp >> 1;       // 2 x 4 warp grid
    const int g = lane >> 2, q = lane & 3;
    const int bm = blockIdx.y * BM, bn = blockIdx.x * BN;

    // loader mapping: 128 rows x 8 16B-chunks, 256 threads -> 4 rows each
    const int lrow = tid >> 3;         // 0..31 (+32*rr)
    const int lcol = tid & 7;          // 16B chunk within 128B row

    const float* gA = A + (size_t)(bm + lrow) * K + lcol * 4;
    const float* gB = W + (size_t)(bn + lrow) * K + lcol * 4;
    const uint32_t sbase = smem_u32(smem);
    const uint32_t sAoff = (lrow * LDSW + lcol * 4) * 4;
    const uint32_t sBoff = sAoff + BM * LDSW * 4;

    const int KT = K / BK;

    auto issue_tile = [&](int stage, int kt) {
        uint32_t sa = sbase + stage * STAGE_FLOATS * 4 + sAoff;
        uint32_t sb = sbase + stage * STAGE_FLOATS * 4 + sBoff;
        const float* pa = gA + kt * BK;
        const float* pb = gB + kt * BK;
#pragma unroll
        for (int rr = 0; rr < 4; rr++) {
            cp_async16(sa + rr * 32 * LDSW * 4, pa + (size_t)rr * 32 * K);
            cp_async16(sb + rr * 32 * LDSW * 4, pb + (size_t)rr * 32 * K);
        }
    };

    float acc[4][4][4];
#pragma unroll
    for (int mi = 0; mi < 4; mi++)
#pragma unroll
        for (int ni = 0; ni < 4; ni++)
#pragma unroll
            for (int r = 0; r < 4; r++) acc[mi][ni][r] = 0.0f;

    // prologue: tiles 0,1
    issue_tile(0, 0); CP_COMMIT();
    if (KT > 1) issue_tile(1, 1);
    CP_COMMIT();

    for (int i = 0; i < KT; i++) {
        if (i + 2 < KT) issue_tile((i + 2) % 3, i + 2);
        CP_COMMIT();
        CP_WAIT2();
        __syncthreads();

        const uint32_t* sA = reinterpret_cast<const uint32_t*>(smem + (i % 3) * STAGE_FLOATS);
        const uint32_t* sB = sA + BM * LDSW;
        const uint32_t* pa0 = sA + (wm * 64 + g) * LDSW + q;
        const uint32_t* pb0 = sB + (wn * 32 + g) * LDSW + q;

#pragma unroll
        for (int kk = 0; kk < 4; kk++) {
            uint32_t a[4][4], b[4][2];
#pragma unroll
            for (int mi = 0; mi < 4; mi++) {
                const uint32_t* p = pa0 + mi * (16 * LDSW) + kk * 8;
                a[mi][0] = p[0];
                a[mi][1] = p[8 * LDSW];
                a[mi][2] = p[4];
                a[mi][3] = p[8 * LDSW + 4];
            }
#pragma unroll
            for (int ni = 0; ni < 4; ni++) {
                const uint32_t* p = pb0 + ni * (8 * LDSW) + kk * 8;
                b[ni][0] = p[0];
                b[ni][1] = p[4];
            }
#pragma unroll
            for (int mi = 0; mi < 4; mi++)
#pragma unroll
                for (int ni = 0; ni < 4; ni++)
                    mma_tf32(acc[mi][ni], a[mi], b[ni]);
        }
        __syncthreads();
    }

    // epilogue: c0,c1 -> (row, 2q),(row, 2q+1); c2,c3 -> row+8
    const int crow = bm + wm * 64 + g;
    const int ccol = bn + wn * 32 + 2 * q;
#pragma unroll
    for (int mi = 0; mi < 4; mi++) {
#pragma unroll
        for (int ni = 0; ni < 4; ni++) {
            float* p0 = C + (size_t)(crow + mi * 16) * N + ccol + ni * 8;
            float* p1 = C + (size_t)(crow + mi * 16 + 8) * N + ccol + ni * 8;
            *reinterpret_cast<float2*>(p0) = make_float2(acc[mi][ni][0], acc[mi][ni][1]);
            *reinterpret_cast<float2*>(p1) = make_float2(acc[mi][ni][2], acc[mi][ni][3]);
        }
    }
}

// ---------------- launch ----------------
extern "C" void kernel_launch(void* const* d_in, const int* in_sizes, int n_in,
                              void* d_out, int out_size) {
    const float* x    = (const float*)d_in[0];
    const float* cbg  = (const float*)d_in[1];
    const int*   idxg = (const int*)  d_in[2];
    const float* scg  = (const float*)d_in[3];
    const float* cbu  = (const float*)d_in[4];
    const int*   idxu = (const int*)  d_in[5];
    const float* scu  = (const float*)d_in[6];
    const float* cbd  = (const float*)d_in[7];
    const int*   idxd = (const int*)  d_in[8];
    const float* scd  = (const float*)d_in[9];
    float* out = (float*)d_out;

    const int M = in_sizes[0] / HIDDEN;   // 4096

    // Resolve REAL device addresses of the __device__ globals (host shadow
    // symbols are NOT device pointers — that was the R7 bug).
    float *p_x, *p_wg, *p_wu, *p_wd, *p_gate, *p_up, *p_h;
    cudaGetSymbolAddress((void**)&p_x,    g_x);
    cudaGetSymbolAddress((void**)&p_wg,   g_wgate);
    cudaGetSymbolAddress((void**)&p_wu,   g_wup);
    cudaGetSymbolAddress((void**)&p_wd,   g_wdown);
    cudaGetSymbolAddress((void**)&p_gate, g_gate);
    cudaGetSymbolAddress((void**)&p_up,   g_up);
    cudaGetSymbolAddress((void**)&p_h,    g_h);

    cudaFuncSetAttribute(gemm_tf32, cudaFuncAttributeMaxDynamicSharedMemorySize, GEMM_SMEM);

    // prep: dequant weights (tf32-rounded) + round x
    {
        int n_gu = INTER * (HIDDEN / VEC);
        int n_d  = HIDDEN * (INTER / VEC);
        int n4   = M * HIDDEN / 4;
        dequant_gate<<<(n_gu + 255) / 256, 256>>>(cbg, idxg, scg);
        dequant_up  <<<(n_gu + 255) / 256, 256>>>(cbu, idxu, scu);
        dequant_down<<<(n_d  + 255) / 256, 256>>>(cbd, idxd, scd);
        convert_x   <<<(n4   + 255) / 256, 256>>>(x, n4);
    }

    // gate = x @ Wg^T ; up = x @ Wu^T
    {
        dim3 grid(INTER / BN, M / BM);
        gemm_tf32<<<grid, 256, GEMM_SMEM>>>(p_x, p_wg, p_gate, M, INTER, HIDDEN);
        gemm_tf32<<<grid, 256, GEMM_SMEM>>>(p_x, p_wu, p_up,   M, INTER, HIDDEN);
    }

    // h = tf32(silu(gate) * up)
    {
        int n4 = M * INTER / 4;
        silu_mul<<<(n4 + 255) / 256, 256>>>(n4);
    }

    // out = h @ Wd^T
    {
        dim3 grid(HIDDEN / BN, M / BM);
        gemm_tf32<<<grid, 256, GEMM_SMEM>>>(p_h, p_wd, out, M, HIDDEN, INTER);
    }
}

// round 15
// speedup vs baseline: 2.2587x; 1.1301x over previous
#include <cuda_runtime.h>
#include <cstdint>

#define HIDDEN 2048
#define INTER  5632
#define VEC    8
#define MAXTOK 4096

// ---------------- scratch (device globals: no allocations) ----------------
__device__ float g_wgate[(size_t)INTER * HIDDEN];
__device__ float g_wup  [(size_t)INTER * HIDDEN];
__device__ float g_wdown[(size_t)HIDDEN * INTER];
__device__ float g_x    [(size_t)MAXTOK * HIDDEN];
__device__ float g_h    [(size_t)MAXTOK * INTER];

// ---------------- helpers ----------------
__device__ __forceinline__ float tf32_rn(float x) {
    uint32_t u = __float_as_uint(x);
    u += 0xFFFu + ((u >> 13) & 1u);   // RN-even into tf32 (data has no inf/nan)
    u &= 0xFFFFE000u;
    return __uint_as_float(u);
}

__device__ __forceinline__ uint32_t smem_u32(const void* p) {
    uint32_t a;
    asm("{ .reg .u64 t; cvta.to.shared.u64 t, %1; cvt.u32.u64 %0, t; }" : "=r"(a) : "l"(p));
    return a;
}

__device__ __forceinline__ void cp_async16(uint32_t s, const void* g) {
    asm volatile("cp.async.cg.shared.global [%0], [%1], 16;" :: "r"(s), "l"(g));
}
#define CP_COMMIT() asm volatile("cp.async.commit_group;" ::: "memory")
#define CP_WAIT1()  asm volatile("cp.async.wait_group 1;" ::: "memory")
#define CP_WAIT2()  asm volatile("cp.async.wait_group 2;" ::: "memory")

__device__ __forceinline__ void mma_tf32(float* c, const uint32_t* a, const uint32_t* b) {
    asm volatile(
        "mma.sync.aligned.m16n8k8.row.col.f32.tf32.tf32.f32 "
        "{%0,%1,%2,%3}, {%4,%5,%6,%7}, {%8,%9}, {%0,%1,%2,%3};"
        : "+f"(c[0]), "+f"(c[1]), "+f"(c[2]), "+f"(c[3])
        : "r"(a[0]), "r"(a[1]), "r"(a[2]), "r"(a[3]), "r"(b[0]), "r"(b[1]));
}

// ---------------- prep kernels (tf32-round everything once) ----------------
__device__ __forceinline__ void dequant_impl(const float* __restrict__ cb,
                                             const int*   __restrict__ idx,
                                             const float* __restrict__ scale,
                                             float*       __restrict__ w,
                                             int rows, int colsv) {
    int t = blockIdx.x * blockDim.x + threadIdx.x;
    if (t >= rows * colsv) return;
    int r = t / colsv;
    int code = idx[t];
    float s = __ldg(scale + r);
    const float4* cv = reinterpret_cast<const float4*>(cb) + (size_t)code * 2;
    float4 lo = cv[0], hi = cv[1];
    float4* out = reinterpret_cast<float4*>(w) + (size_t)t * 2;
    out[0] = make_float4(tf32_rn(lo.x * s), tf32_rn(lo.y * s), tf32_rn(lo.z * s), tf32_rn(lo.w * s));
    out[1] = make_float4(tf32_rn(hi.x * s), tf32_rn(hi.y * s), tf32_rn(hi.z * s), tf32_rn(hi.w * s));
}
__global__ void dequant_gate(const float* cb, const int* idx, const float* sc) {
    dequant_impl(cb, idx, sc, g_wgate, INTER, HIDDEN / VEC);
}
__global__ void dequant_up(const float* cb, const int* idx, const float* sc) {
    dequant_impl(cb, idx, sc, g_wup, INTER, HIDDEN / VEC);
}
__global__ void dequant_down(const float* cb, const int* idx, const float* sc) {
    dequant_impl(cb, idx, sc, g_wdown, HIDDEN, INTER / VEC);
}
__global__ void convert_x(const float* __restrict__ x, int n4) {
    int t = blockIdx.x * blockDim.x + threadIdx.x;
    if (t >= n4) return;
    float4 v = reinterpret_cast<const float4*>(x)[t];
    reinterpret_cast<float4*>(g_x)[t] =
        make_float4(tf32_rn(v.x), tf32_rn(v.y), tf32_rn(v.z), tf32_rn(v.w));
}

// ======================= fused GEMM1: h = tf32(silu(x@Wg^T) * (x@Wu^T)) =======================
// Same envelope as the validated R12 kernel: 256 threads, 108 KB smem.
// CTA 128x128, BK=32, 2-stage x 3-tile (A,Bg,Bu) cp.async pipeline.
// 8 warps (2m x 4n); warp tile 64x32 applied to BOTH gate and up (A frags shared).
#define BM 128
#define BN 128
#define BK 32
#define LDSW 36
#define TILE_FLOATS (BM * LDSW)              // one 128x32 padded tile
#define GU_STAGE (3 * TILE_FLOATS)           // A + Bg + Bu
#define GU_SMEM  (2 * GU_STAGE * 4)          // 2 stages = 108 KB

__global__ __launch_bounds__(256, 1) void gemm_gateup(const float* __restrict__ A,
                                                      const float* __restrict__ Wg,
                                                      const float* __restrict__ Wu,
                                                      float* __restrict__ H,
                                                      int M) {
    extern __shared__ float smem[];
    const int K = HIDDEN, N = INTER;
    const int tid = threadIdx.x;
    const int warp = tid >> 5, lane = tid & 31;
    const int wm = warp & 1, wn = warp >> 1;          // 2 x 4 warp grid
    const int g = lane >> 2, q = lane & 3;
    const int bm = blockIdx.y * BM, bn = blockIdx.x * BN;

    // loader: 256 threads cover 32 rows x 8 chunks; rr in {0..3} adds +32 rows
    const int lrow = tid >> 3;          // 0..31
    const int lcol = tid & 7;

    const float* gA = A  + (size_t)(bm + lrow) * K + lcol * 4;
    const float* gG = Wg + (size_t)(bn + lrow) * K + lcol * 4;
    const float* gU = Wu + (size_t)(bn + lrow) * K + lcol * 4;
    const uint32_t sbase = smem_u32(smem);
    const uint32_t soff = (lrow * LDSW + lcol * 4) * 4;

    const int KT = K / BK;

    auto issue_tile = [&](int stage, int kt) {
        uint32_t sa = sbase + stage * GU_STAGE * 4 + soff;
        const float* pa = gA + kt * BK;
        const float* pg = gG + kt * BK;
        const float* pu = gU + kt * BK;
#pragma unroll
        for (int rr = 0; rr < 4; rr++) {
            cp_async16(sa + (rr * 32 * LDSW) * 4,                    pa + (size_t)rr * 32 * K);
            cp_async16(sa + (TILE_FLOATS + rr * 32 * LDSW) * 4,      pg + (size_t)rr * 32 * K);
            cp_async16(sa + (2 * TILE_FLOATS + rr * 32 * LDSW) * 4,  pu + (size_t)rr * 32 * K);
        }
    };

    float accg[4][4][4], accu[4][4][4];
#pragma unroll
    for (int mi = 0; mi < 4; mi++)
#pragma unroll
        for (int ni = 0; ni < 4; ni++)
#pragma unroll
            for (int r = 0; r < 4; r++) { accg[mi][ni][r] = 0.0f; accu[mi][ni][r] = 0.0f; }

    issue_tile(0, 0); CP_COMMIT();

    for (int i = 0; i < KT; i++) {
        if (i + 1 < KT) issue_tile((i + 1) & 1, i + 1);
        CP_COMMIT();
        CP_WAIT1();          // newest group may be in flight; tile i is complete
        __syncthreads();

        const uint32_t* sA = reinterpret_cast<const uint32_t*>(smem + (i & 1) * GU_STAGE);
        const uint32_t* sG = sA + TILE_FLOATS;
        const uint32_t* sU = sG + TILE_FLOATS;
        const uint32_t* pa0 = sA + (wm * 64 + g) * LDSW + q;
        const uint32_t* pg0 = sG + (wn * 32 + g) * LDSW + q;
        const uint32_t* pu0 = sU + (wn * 32 + g) * LDSW + q;

#pragma unroll
        for (int kk = 0; kk < 4; kk++) {
            uint32_t a[4][4], bg[4][2], bu[4][2];
#pragma unroll
            for (int mi = 0; mi < 4; mi++) {
                const uint32_t* p = pa0 + mi * (16 * LDSW) + kk * 8;
                a[mi][0] = p[0];
                a[mi][1] = p[8 * LDSW];
                a[mi][2] = p[4];
                a[mi][3] = p[8 * LDSW + 4];
            }
#pragma unroll
            for (int ni = 0; ni < 4; ni++) {
                const uint32_t* pg = pg0 + ni * (8 * LDSW) + kk * 8;
                const uint32_t* pu = pu0 + ni * (8 * LDSW) + kk * 8;
                bg[ni][0] = pg[0]; bg[ni][1] = pg[4];
                bu[ni][0] = pu[0]; bu[ni][1] = pu[4];
            }
#pragma unroll
            for (int mi = 0; mi < 4; mi++)
#pragma unroll
                for (int ni = 0; ni < 4; ni++) {
                    mma_tf32(accg[mi][ni], a[mi], bg[ni]);
                    mma_tf32(accu[mi][ni], a[mi], bu[ni]);
                }
        }
        __syncthreads();
    }

    // epilogue: h = tf32_rn(silu(g) * u)
    const int crow = bm + wm * 64 + g;
    const int ccol = bn + wn * 32 + 2 * q;
#pragma unroll
    for (int mi = 0; mi < 4; mi++) {
#pragma unroll
        for (int ni = 0; ni < 4; ni++) {
            float h0 = accg[mi][ni][0], h1 = accg[mi][ni][1];
            float h2 = accg[mi][ni][2], h3 = accg[mi][ni][3];
            h0 = tf32_rn(h0 / (1.0f + expf(-h0)) * accu[mi][ni][0]);
            h1 = tf32_rn(h1 / (1.0f + expf(-h1)) * accu[mi][ni][1]);
            h2 = tf32_rn(h2 / (1.0f + expf(-h2)) * accu[mi][ni][2]);
            h3 = tf32_rn(h3 / (1.0f + expf(-h3)) * accu[mi][ni][3]);
            float* p0 = H + (size_t)(crow + mi * 16) * N + ccol + ni * 8;
            float* p1 = H + (size_t)(crow + mi * 16 + 8) * N + ccol + ni * 8;
            *reinterpret_cast<float2*>(p0) = make_float2(h0, h1);
            *reinterpret_cast<float2*>(p1) = make_float2(h2, h3);
        }
    }
}

// ======================= GEMM2: out = h @ Wd^T (validated R12 config, unchanged) =======================
#define STAGE_FLOATS (2 * BM * LDSW)
#define GEMM_SMEM (3 * STAGE_FLOATS * 4)

__global__ __launch_bounds__(256, 1) void gemm_tf32(const float* __restrict__ A,
                                                    const float* __restrict__ W,
                                                    float* __restrict__ C,
                                                    int M, int N, int K) {
    extern __shared__ float smem[];
    const int tid = threadIdx.x;
    const int warp = tid >> 5, lane = tid & 31;
    const int wm = warp & 1, wn = warp >> 1;
    const int g = lane >> 2, q = lane & 3;
    const int bm = blockIdx.y * BM, bn = blockIdx.x * BN;

    const int lrow = tid >> 3;
    const int lcol = tid & 7;

    const float* gA = A + (size_t)(bm + lrow) * K + lcol * 4;
    const float* gB = W + (size_t)(bn + lrow) * K + lcol * 4;
    const uint32_t sbase = smem_u32(smem);
    const uint32_t sAoff = (lrow * LDSW + lcol * 4) * 4;
    const uint32_t sBoff = sAoff + BM * LDSW * 4;

    const int KT = K / BK;

    auto issue_tile = [&](int stage, int kt) {
        uint32_t sa = sbase + stage * STAGE_FLOATS * 4 + sAoff;
        uint32_t sb = sbase + stage * STAGE_FLOATS * 4 + sBoff;
        const float* pa = gA + kt * BK;
        const float* pb = gB + kt * BK;
#pragma unroll
        for (int rr = 0; rr < 4; rr++) {
            cp_async16(sa + rr * 32 * LDSW * 4, pa + (size_t)rr * 32 * K);
            cp_async16(sb + rr * 32 * LDSW * 4, pb + (size_t)rr * 32 * K);
        }
    };

    float acc[4][4][4];
#pragma unroll
    for (int mi = 0; mi < 4; mi++)
#pragma unroll
        for (int ni = 0; ni < 4; ni++)
#pragma unroll
            for (int r = 0; r < 4; r++) acc[mi][ni][r] = 0.0f;

    issue_tile(0, 0); CP_COMMIT();
    issue_tile(1, 1); CP_COMMIT();

    for (int i = 0; i < KT; i++) {
        if (i + 2 < KT) issue_tile((i + 2) % 3, i + 2);
        CP_COMMIT();
        CP_WAIT2();
        __syncthreads();

        const uint32_t* sA = reinterpret_cast<const uint32_t*>(smem + (i % 3) * STAGE_FLOATS);
        const uint32_t* sB = sA + BM * LDSW;
        const uint32_t* pa0 = sA + (wm * 64 + g) * LDSW + q;
        const uint32_t* pb0 = sB + (wn * 32 + g) * LDSW + q;

#pragma unroll
        for (int kk = 0; kk < 4; kk++) {
            uint32_t a[4][4], b[4][2];
#pragma unroll
            for (int mi = 0; mi < 4; mi++) {
                const uint32_t* p = pa0 + mi * (16 * LDSW) + kk * 8;
                a[mi][0] = p[0];
                a[mi][1] = p[8 * LDSW];
                a[mi][2] = p[4];
                a[mi][3] = p[8 * LDSW + 4];
            }
#pragma unroll
            for (int ni = 0; ni < 4; ni++) {
                const uint32_t* p = pb0 + ni * (8 * LDSW) + kk * 8;
                b[ni][0] = p[0];
                b[ni][1] = p[4];
            }
#pragma unroll
            for (int mi = 0; mi < 4; mi++)
#pragma unroll
                for (int ni = 0; ni < 4; ni++)
                    mma_tf32(acc[mi][ni], a[mi], b[ni]);
        }
        __syncthreads();
    }

    const int crow = bm + wm * 64 + g;
    const int ccol = bn + wn * 32 + 2 * q;
#pragma unroll
    for (int mi = 0; mi < 4; mi++) {
#pragma unroll
        for (int ni = 0; ni < 4; ni++) {
            float* p0 = C + (size_t)(crow + mi * 16) * N + ccol + ni * 8;
            float* p1 = C + (size_t)(crow + mi * 16 + 8) * N + ccol + ni * 8;
            *reinterpret_cast<float2*>(p0) = make_float2(acc[mi][ni][0], acc[mi][ni][1]);
            *reinterpret_cast<float2*>(p1) = make_float2(acc[mi][ni][2], acc[mi][ni][3]);
        }
    }
}

// ---------------- launch ----------------
extern "C" void kernel_launch(void* const* d_in, const int* in_sizes, int n_in,
                              void* d_out, int out_size) {
    const float* x    = (const float*)d_in[0];
    const float* cbg  = (const float*)d_in[1];
    const int*   idxg = (const int*)  d_in[2];
    const float* scg  = (const float*)d_in[3];
    const float* cbu  = (const float*)d_in[4];
    const int*   idxu = (const int*)  d_in[5];
    const float* scu  = (const float*)d_in[6];
    const float* cbd  = (const float*)d_in[7];
    const int*   idxd = (const int*)  d_in[8];
    const float* scd  = (const float*)d_in[9];
    float* out = (float*)d_out;

    const int M = in_sizes[0] / HIDDEN;   // 4096

    // real device addresses of the __device__ globals
    float *p_x, *p_wg, *p_wu, *p_wd, *p_h;
    cudaGetSymbolAddress((void**)&p_x,  g_x);
    cudaGetSymbolAddress((void**)&p_wg, g_wgate);
    cudaGetSymbolAddress((void**)&p_wu, g_wup);
    cudaGetSymbolAddress((void**)&p_wd, g_wdown);
    cudaGetSymbolAddress((void**)&p_h,  g_h);

    cudaFuncSetAttribute(gemm_gateup, cudaFuncAttributeMaxDynamicSharedMemorySize, GU_SMEM);
    cudaFuncSetAttribute(gemm_tf32,   cudaFuncAttributeMaxDynamicSharedMemorySize, GEMM_SMEM);

    // prep: dequant weights (tf32-rounded) + round x
    {
        int n_gu = INTER * (HIDDEN / VEC);
        int n_d  = HIDDEN * (INTER / VEC);
        int n4   = M * HIDDEN / 4;
        dequant_gate<<<(n_gu + 255) / 256, 256>>>(cbg, idxg, scg);
        dequant_up  <<<(n_gu + 255) / 256, 256>>>(cbu, idxu, scu);
        dequant_down<<<(n_d  + 255) / 256, 256>>>(cbd, idxd, scd);
        convert_x   <<<(n4   + 255) / 256, 256>>>(x, n4);
    }

    // fused: h = tf32(silu(x@Wg^T) * (x@Wu^T))
    {
        dim3 grid(INTER / BN, M / BM);
        gemm_gateup<<<grid, 256, GU_SMEM>>>(p_x, p_wg, p_wu, p_h, M);
    }

    // out = h @ Wd^T
    {
        dim3 grid(HIDDEN / BN, M / BM);
        gemm_tf32<<<grid, 256, GEMM_SMEM>>>(p_h, p_wd, out, M, HIDDEN, INTER);
    }
}

// round 17
// speedup vs baseline: 2.3730x; 1.0506x over previous
#include <cuda_runtime.h>
#include <cstdint>

#define HIDDEN 2048
#define INTER  5632
#define VEC    8
#define MAXTOK 4096

// ---------------- scratch (device globals: no allocations) ----------------
__device__ float g_wgate[(size_t)INTER * HIDDEN];
__device__ float g_wup  [(size_t)INTER * HIDDEN];
__device__ float g_wdown[(size_t)HIDDEN * INTER];
__device__ float g_x    [(size_t)MAXTOK * HIDDEN];
__device__ float g_h    [(size_t)MAXTOK * INTER];

// ---------------- helpers ----------------
__device__ __forceinline__ float tf32_rn(float x) {
    uint32_t u = __float_as_uint(x);
    u += 0xFFFu + ((u >> 13) & 1u);   // RN-even into tf32 (data has no inf/nan)
    u &= 0xFFFFE000u;
    return __uint_as_float(u);
}

__device__ __forceinline__ uint32_t smem_u32(const void* p) {
    uint32_t a;
    asm("{ .reg .u64 t; cvta.to.shared.u64 t, %1; cvt.u32.u64 %0, t; }" : "=r"(a) : "l"(p));
    return a;
}

__device__ __forceinline__ void cp_async16(uint32_t s, const void* g) {
    asm volatile("cp.async.cg.shared.global [%0], [%1], 16;" :: "r"(s), "l"(g));
}
#define CP_COMMIT() asm volatile("cp.async.commit_group;" ::: "memory")
#define CP_WAIT1()  asm volatile("cp.async.wait_group 1;" ::: "memory")
#define CP_WAIT2()  asm volatile("cp.async.wait_group 2;" ::: "memory")

__device__ __forceinline__ void mma_tf32(float* c, const uint32_t* a, const uint32_t* b) {
    asm volatile(
        "mma.sync.aligned.m16n8k8.row.col.f32.tf32.tf32.f32 "
        "{%0,%1,%2,%3}, {%4,%5,%6,%7}, {%8,%9}, {%0,%1,%2,%3};"
        : "+f"(c[0]), "+f"(c[1]), "+f"(c[2]), "+f"(c[3])
        : "r"(a[0]), "r"(a[1]), "r"(a[2]), "r"(a[3]), "r"(b[0]), "r"(b[1]));
}

// ---------------- prep kernels (tf32-round everything once) ----------------
__device__ __forceinline__ void dequant_impl(const float* __restrict__ cb,
                                             const int*   __restrict__ idx,
                                             const float* __restrict__ scale,
                                             float*       __restrict__ w,
                                             int rows, int colsv) {
    int t = blockIdx.x * blockDim.x + threadIdx.x;
    if (t >= rows * colsv) return;
    int r = t / colsv;
    int code = idx[t];
    float s = __ldg(scale + r);
    const float4* cv = reinterpret_cast<const float4*>(cb) + (size_t)code * 2;
    float4 lo = cv[0], hi = cv[1];
    float4* out = reinterpret_cast<float4*>(w) + (size_t)t * 2;
    out[0] = make_float4(tf32_rn(lo.x * s), tf32_rn(lo.y * s), tf32_rn(lo.z * s), tf32_rn(lo.w * s));
    out[1] = make_float4(tf32_rn(hi.x * s), tf32_rn(hi.y * s), tf32_rn(hi.z * s), tf32_rn(hi.w * s));
}
__global__ void dequant_gate(const float* cb, const int* idx, const float* sc) {
    dequant_impl(cb, idx, sc, g_wgate, INTER, HIDDEN / VEC);
}
__global__ void dequant_up(const float* cb, const int* idx, const float* sc) {
    dequant_impl(cb, idx, sc, g_wup, INTER, HIDDEN / VEC);
}
__global__ void dequant_down(const float* cb, const int* idx, const float* sc) {
    dequant_impl(cb, idx, sc, g_wdown, HIDDEN, INTER / VEC);
}
// grid-stride, 4x float4 per thread per iter
__global__ void convert_x(const float* __restrict__ x, int n4) {
    int stride = gridDim.x * blockDim.x;
    for (int t = blockIdx.x * blockDim.x + threadIdx.x; t < n4; t += stride) {
        float4 v = reinterpret_cast<const float4*>(x)[t];
        reinterpret_cast<float4*>(g_x)[t] =
            make_float4(tf32_rn(v.x), tf32_rn(v.y), tf32_rn(v.z), tf32_rn(v.w));
    }
}

// ======================= fused GEMM1: h = tf32(silu(x@Wg^T) * (x@Wu^T)) =======================
// Validated R15 config (unchanged): 256 threads, 108 KB smem, CTA 128x128, BK=32,
// 2-stage x 3-tile (A,Bg,Bu) cp.async pipeline, 8 warps (2m x 4n), warp tile 64x32 on both.
#define BM 128
#define BN 128
#define BK 32
#define LDSW 36
#define TILE_FLOATS (BM * LDSW)
#define GU_STAGE (3 * TILE_FLOATS)
#define GU_SMEM  (2 * GU_STAGE * 4)

__global__ __launch_bounds__(256, 1) void gemm_gateup(const float* __restrict__ A,
                                                      const float* __restrict__ Wg,
                                                      const float* __restrict__ Wu,
                                                      float* __restrict__ H,
                                                      int M) {
    extern __shared__ float smem[];
    const int K = HIDDEN, N = INTER;
    const int tid = threadIdx.x;
    const int warp = tid >> 5, lane = tid & 31;
    const int wm = warp & 1, wn = warp >> 1;
    const int g = lane >> 2, q = lane & 3;
    const int bm = blockIdx.y * BM, bn = blockIdx.x * BN;

    const int lrow = tid >> 3;
    const int lcol = tid & 7;

    const float* gA = A  + (size_t)(bm + lrow) * K + lcol * 4;
    const float* gG = Wg + (size_t)(bn + lrow) * K + lcol * 4;
    const float* gU = Wu + (size_t)(bn + lrow) * K + lcol * 4;
    const uint32_t sbase = smem_u32(smem);
    const uint32_t soff = (lrow * LDSW + lcol * 4) * 4;

    const int KT = K / BK;

    auto issue_tile = [&](int stage, int kt) {
        uint32_t sa = sbase + stage * GU_STAGE * 4 + soff;
        const float* pa = gA + kt * BK;
        const float* pg = gG + kt * BK;
        const float* pu = gU + kt * BK;
#pragma unroll
        for (int rr = 0; rr < 4; rr++) {
            cp_async16(sa + (rr * 32 * LDSW) * 4,                    pa + (size_t)rr * 32 * K);
            cp_async16(sa + (TILE_FLOATS + rr * 32 * LDSW) * 4,      pg + (size_t)rr * 32 * K);
            cp_async16(sa + (2 * TILE_FLOATS + rr * 32 * LDSW) * 4,  pu + (size_t)rr * 32 * K);
        }
    };

    float accg[4][4][4], accu[4][4][4];
#pragma unroll
    for (int mi = 0; mi < 4; mi++)
#pragma unroll
        for (int ni = 0; ni < 4; ni++)
#pragma unroll
            for (int r = 0; r < 4; r++) { accg[mi][ni][r] = 0.0f; accu[mi][ni][r] = 0.0f; }

    issue_tile(0, 0); CP_COMMIT();

    for (int i = 0; i < KT; i++) {
        if (i + 1 < KT) issue_tile((i + 1) & 1, i + 1);
        CP_COMMIT();
        CP_WAIT1();
        __syncthreads();

        const uint32_t* sA = reinterpret_cast<const uint32_t*>(smem + (i & 1) * GU_STAGE);
        const uint32_t* sG = sA + TILE_FLOATS;
        const uint32_t* sU = sG + TILE_FLOATS;
        const uint32_t* pa0 = sA + (wm * 64 + g) * LDSW + q;
        const uint32_t* pg0 = sG + (wn * 32 + g) * LDSW + q;
        const uint32_t* pu0 = sU + (wn * 32 + g) * LDSW + q;

#pragma unroll
        for (int kk = 0; kk < 4; kk++) {
            uint32_t a[4][4], bg[4][2], bu[4][2];
#pragma unroll
            for (int mi = 0; mi < 4; mi++) {
                const uint32_t* p = pa0 + mi * (16 * LDSW) + kk * 8;
                a[mi][0] = p[0];
                a[mi][1] = p[8 * LDSW];
                a[mi][2] = p[4];
                a[mi][3] = p[8 * LDSW + 4];
            }
#pragma unroll
            for (int ni = 0; ni < 4; ni++) {
                const uint32_t* pg = pg0 + ni * (8 * LDSW) + kk * 8;
                const uint32_t* pu = pu0 + ni * (8 * LDSW) + kk * 8;
                bg[ni][0] = pg[0]; bg[ni][1] = pg[4];
                bu[ni][0] = pu[0]; bu[ni][1] = pu[4];
            }
#pragma unroll
            for (int mi = 0; mi < 4; mi++)
#pragma unroll
                for (int ni = 0; ni < 4; ni++) {
                    mma_tf32(accg[mi][ni], a[mi], bg[ni]);
                    mma_tf32(accu[mi][ni], a[mi], bu[ni]);
                }
        }
        __syncthreads();
    }

    const int crow = bm + wm * 64 + g;
    const int ccol = bn + wn * 32 + 2 * q;
#pragma unroll
    for (int mi = 0; mi < 4; mi++) {
#pragma unroll
        for (int ni = 0; ni < 4; ni++) {
            float h0 = accg[mi][ni][0], h1 = accg[mi][ni][1];
            float h2 = accg[mi][ni][2], h3 = accg[mi][ni][3];
            h0 = tf32_rn(h0 / (1.0f + expf(-h0)) * accu[mi][ni][0]);
            h1 = tf32_rn(h1 / (1.0f + expf(-h1)) * accu[mi][ni][1]);
            h2 = tf32_rn(h2 / (1.0f + expf(-h2)) * accu[mi][ni][2]);
            h3 = tf32_rn(h3 / (1.0f + expf(-h3)) * accu[mi][ni][3]);
            float* p0 = H + (size_t)(crow + mi * 16) * N + ccol + ni * 8;
            float* p1 = H + (size_t)(crow + mi * 16 + 8) * N + ccol + ni * 8;
            *reinterpret_cast<float2*>(p0) = make_float2(h0, h1);
            *reinterpret_cast<float2*>(p1) = make_float2(h2, h3);
        }
    }
}

// ======================= GEMM2: out = h @ Wd^T (R12 config, now occupancy 2) =======================
#define STAGE_FLOATS (2 * BM * LDSW)
#define GEMM_SMEM (3 * STAGE_FLOATS * 4)

__global__ __launch_bounds__(256, 2) void gemm_tf32(const float* __restrict__ A,
                                                    const float* __restrict__ W,
                                                    float* __restrict__ C,
                                                    int M, int N, int K) {
    extern __shared__ float smem[];
    const int tid = threadIdx.x;
    const int warp = tid >> 5, lane = tid & 31;
    const int wm = warp & 1, wn = warp >> 1;
    const int g = lane >> 2, q = lane & 3;
    const int bm = blockIdx.y * BM, bn = blockIdx.x * BN;

    const int lrow = tid >> 3;
    const int lcol = tid & 7;

    const float* gA = A + (size_t)(bm + lrow) * K + lcol * 4;
    const float* gB = W + (size_t)(bn + lrow) * K + lcol * 4;
    const uint32_t sbase = smem_u32(smem);
    const uint32_t sAoff = (lrow * LDSW + lcol * 4) * 4;
    const uint32_t sBoff = sAoff + BM * LDSW * 4;

    const int KT = K / BK;

    auto issue_tile = [&](int stage, int kt) {
        uint32_t sa = sbase + stage * STAGE_FLOATS * 4 + sAoff;
        uint32_t sb = sbase + stage * STAGE_FLOATS * 4 + sBoff;
        const float* pa = gA + kt * BK;
        const float* pb = gB + kt * BK;
#pragma unroll
        for (int rr = 0; rr < 4; rr++) {
            cp_async16(sa + rr * 32 * LDSW * 4, pa + (size_t)rr * 32 * K);
            cp_async16(sb + rr * 32 * LDSW * 4, pb + (size_t)rr * 32 * K);
        }
    };

    float acc[4][4][4];
#pragma unroll
    for (int mi = 0; mi < 4; mi++)
#pragma unroll
        for (int ni = 0; ni < 4; ni++)
#pragma unroll
            for (int r = 0; r < 4; r++) acc[mi][ni][r] = 0.0f;

    issue_tile(0, 0); CP_COMMIT();
    issue_tile(1, 1); CP_COMMIT();

    for (int i = 0; i < KT; i++) {
        if (i + 2 < KT) issue_tile((i + 2) % 3, i + 2);
        CP_COMMIT();
        CP_WAIT2();
        __syncthreads();

        const uint32_t* sA = reinterpret_cast<const uint32_t*>(smem + (i % 3) * STAGE_FLOATS);
        const uint32_t* sB = sA + BM * LDSW;
        const uint32_t* pa0 = sA + (wm * 64 + g) * LDSW + q;
        const uint32_t* pb0 = sB + (wn * 32 + g) * LDSW + q;

#pragma unroll
        for (int kk = 0; kk < 4; kk++) {
            uint32_t a[4][4], b[4][2];
#pragma unroll
            for (int mi = 0; mi < 4; mi++) {
                const uint32_t* p = pa0 + mi * (16 * LDSW) + kk * 8;
                a[mi][0] = p[0];
                a[mi][1] = p[8 * LDSW];
                a[mi][2] = p[4];
                a[mi][3] = p[8 * LDSW + 4];
            }
#pragma unroll
            for (int ni = 0; ni < 4; ni++) {
                const uint32_t* p = pb0 + ni * (8 * LDSW) + kk * 8;
                b[ni][0] = p[0];
                b[ni][1] = p[4];
            }
#pragma unroll
            for (int mi = 0; mi < 4; mi++)
#pragma unroll
                for (int ni = 0; ni < 4; ni++)
                    mma_tf32(acc[mi][ni], a[mi], b[ni]);
        }
        __syncthreads();
    }

    const int crow = bm + wm * 64 + g;
    const int ccol = bn + wn * 32 + 2 * q;
#pragma unroll
    for (int mi = 0; mi < 4; mi++) {
#pragma unroll
        for (int ni = 0; ni < 4; ni++) {
            float* p0 = C + (size_t)(crow + mi * 16) * N + ccol + ni * 8;
            float* p1 = C + (size_t)(crow + mi * 16 + 8) * N + ccol + ni * 8;
            *reinterpret_cast<float2*>(p0) = make_float2(acc[mi][ni][0], acc[mi][ni][1]);
            *reinterpret_cast<float2*>(p1) = make_float2(acc[mi][ni][2], acc[mi][ni][3]);
        }
    }
}

// ---------------- launch ----------------
extern "C" void kernel_launch(void* const* d_in, const int* in_sizes, int n_in,
                              void* d_out, int out_size) {
    const float* x    = (const float*)d_in[0];
    const float* cbg  = (const float*)d_in[1];
    const int*   idxg = (const int*)  d_in[2];
    const float* scg  = (const float*)d_in[3];
    const float* cbu  = (const float*)d_in[4];
    const int*   idxu = (const int*)  d_in[5];
    const float* scu  = (const float*)d_in[6];
    const float* cbd  = (const float*)d_in[7];
    const int*   idxd = (const int*)  d_in[8];
    const float* scd  = (const float*)d_in[9];
    float* out = (float*)d_out;

    const int M = in_sizes[0] / HIDDEN;   // 4096

    // real device addresses of the __device__ globals
    float *p_x, *p_wg, *p_wu, *p_wd, *p_h;
    cudaGetSymbolAddress((void**)&p_x,  g_x);
    cudaGetSymbolAddress((void**)&p_wg, g_wgate);
    cudaGetSymbolAddress((void**)&p_wu, g_wup);
    cudaGetSymbolAddress((void**)&p_wd, g_wdown);
    cudaGetSymbolAddress((void**)&p_h,  g_h);

    cudaFuncSetAttribute(gemm_gateup, cudaFuncAttributeMaxDynamicSharedMemorySize, GU_SMEM);
    cudaFuncSetAttribute(gemm_tf32,   cudaFuncAttributeMaxDynamicSharedMemorySize, GEMM_SMEM);

    const int n_gu = INTER * (HIDDEN / VEC);
    const int n_d  = HIDDEN * (INTER / VEC);
    const int n4   = M * HIDDEN / 4;

    // launch order chosen so gemm_gateup lands in the ncu-profiled slot,
    // and dequant_down (only needed by gemm_down) runs after gateup.
    convert_x   <<<592, 256>>>(x, n4);                          // 1
    dequant_gate<<<(n_gu + 255) / 256, 256>>>(cbg, idxg, scg);  // 2
    dequant_up  <<<(n_gu + 255) / 256, 256>>>(cbu, idxu, scu);  // 3

    {   // 4: fused h = tf32(silu(x@Wg^T) * (x@Wu^T))
        dim3 grid(INTER / BN, M / BM);
        gemm_gateup<<<grid, 256, GU_SMEM>>>(p_x, p_wg, p_wu, p_h, M);
    }

    dequant_down<<<(n_d + 255) / 256, 256>>>(cbd, idxd, scd);   // 5

    {   // 6: out = h @ Wd^T
        dim3 grid(HIDDEN / BN, M / BM);
        gemm_tf32<<<grid, 256, GEMM_SMEM>>>(p_h, p_wd, out, M, HIDDEN, INTER);
    }
}